// round 10
// baseline (speedup 1.0000x reference)
#include <cuda_runtime.h>
#include <math_constants.h>
#include <cstdint>

// SPP: out = concat(x, pool5(x), pool9(x), pool13(x)) along channels.
// Cascade: pool9 = pool5(pool5(x)), pool13 = pool5(pool9(x)), separable.
//
// Structure: block = 8 contiguous planes, 4 warps; compute core = R3
// (warp = 2 planes, width-16 shuffles, pair-max horizontal 5-max,
// register-ring vertical 5-max, in-place cascade).
//
// R9: hybrid drain.
//  - Section 0 (pass-through): direct STG.64 from registers immediately
//    after the load — no staging, no barrier, drains via the LSU path
//    while everything else happens.
//  - Sections 1-3 (pools): ONE 32 KB cp.async.bulk per section with
//    L2 evict_first (R8 win), double-buffered, recycle-wait hoisted ahead
//    of the compute phase. Bulk engine path.
//  Two independent write paths supply L2/DRAM concurrently.
//
// x: (32, 512, 32, 32) f32 -> out: (32, 2048, 32, 32) f32.

#define NCHAN 512
#define HW 1024
#define PLANES (32 * 512)
#define WARPS_PER_BLK 4
#define PLANES_PER_BLK (WARPS_PER_BLK * 2)
#define SEC_FLOATS (PLANES_PER_BLK * HW)          // 8192 floats
#define SEC_BYTES  (SEC_FLOATS * 4)               // 32768 bytes
#define SMEM_BYTES (2 * SEC_BYTES)                // 64 KB

__device__ __forceinline__ uint32_t smem_u32(const void* p) {
    uint32_t a;
    asm("{ .reg .u64 t; cvta.to.shared.u64 t, %1; cvt.u32.u64 %0, t; }"
        : "=r"(a) : "l"(p));
    return a;
}

__device__ __forceinline__ void bulk_store_ef(const float* dst, uint32_t s) {
    asm volatile(
        "{\n\t"
        ".reg .b64 pol;\n\t"
        "createpolicy.fractional.L2::evict_first.b64 pol, 1.0;\n\t"
        "cp.async.bulk.global.shared::cta.bulk_group.L2::cache_hint "
        "[%0], [%1], %2, pol;\n\t"
        "}"
        :: "l"(dst), "r"(s), "n"(SEC_BYTES) : "memory");
    asm volatile("cp.async.bulk.commit_group;" ::: "memory");
}

__global__ __launch_bounds__(32 * WARPS_PER_BLK)
void spp_kernel(const float* __restrict__ x, float* __restrict__ out) {
    extern __shared__ float sbuf[];               // [2][SEC_FLOATS]

    const int lane = threadIdx.x & 31;
    const int wid  = threadIdx.x >> 5;
    const int sub  = lane >> 4;                   // plane within warp (0/1)
    const int l    = lane & 15;                   // column-pair index

    const int pl_local = wid * 2 + sub;           // 0..7 within block
    const int plane = blockIdx.x * PLANES_PER_BLK + pl_local;   // n*512+c
    const int n  = plane >> 9;
    const int c0 = (blockIdx.x * PLANES_PER_BLK) & (NCHAN - 1);

    const float2* __restrict__ xin =
        (const float2*)(x + (size_t)plane * HW) + l;
    // Block-base output pointer (for bulk sections 1..3).
    const float* __restrict__ ob =
        out + ((size_t)n * (4 * NCHAN) + c0) * HW;
    // Per-thread output pointer for the direct section-0 store.
    float2* __restrict__ ob0 =
        (float2*)(out + ((size_t)n * (4 * NCHAN) + (plane & (NCHAN - 1))) * HW) + l;

    // Load lane's 2-column strip; section-0 pass-through stores issue
    // immediately (fire-and-forget on the LSU path).
    float2 v[32];
    #pragma unroll
    for (int y = 0; y < 32; ++y) {
        v[y] = xin[y * 16];
        ob0[y * 16] = v[y];
    }

    float2* stg0 = (float2*)(sbuf)              + pl_local * (HW / 2) + l;
    float2* stg1 = (float2*)(sbuf + SEC_FLOATS) + pl_local * (HW / 2) + l;
    const uint32_t s0 = smem_u32(sbuf);
    const uint32_t s1 = smem_u32(sbuf + SEC_FLOATS);

    const unsigned FULL = 0xffffffffu;
    const float NEG = -CUDART_INF_F;

    #pragma unroll
    for (int p = 0; p < 3; ++p) {
        // Buffer for section p+1: 0,1,0. Its previous bulk consumer (if any)
        // was issued two sections ago; poll now so the wait hides under the
        // compute phase below.
        const int b = p & 1;                      // stage buffers: 0,1,0
        if (p == 2 && threadIdx.x == 0)
            asm volatile("cp.async.bulk.wait_group.read 1;" ::: "memory");

        // ---- compute pool p entirely in registers ----
        float2 r0 = {NEG, NEG}, r1 = {NEG, NEG},
               r2 = {NEG, NEG}, r3 = {NEG, NEG};

        #pragma unroll
        for (int y = 0; y < 34; ++y) {
            float2 h;
            if (y < 32) {
                const float a = v[y].x, bb = v[y].y;
                const float pm = fmaxf(a, bb);
                const float lp = __shfl_up_sync  (FULL, pm, 1, 16);
                const float lb = __shfl_up_sync  (FULL, bb, 1, 16);
                const float ra = __shfl_down_sync(FULL, a,  1, 16);
                const float rp = __shfl_down_sync(FULL, pm, 1, 16);
                h.x = fmaxf(fmaxf(lp, pm), ra);   // cols 2l-2 .. 2l+2
                h.y = fmaxf(fmaxf(lb, pm), rp);   // cols 2l-1 .. 2l+3
            } else {
                h.x = NEG; h.y = NEG;             // bottom padding rows
            }
            if (y >= 2) {
                float2 m;
                m.x = fmaxf(fmaxf(fmaxf(r0.x, r1.x), fmaxf(r2.x, r3.x)), h.x);
                m.y = fmaxf(fmaxf(fmaxf(r0.y, r1.y), fmaxf(r2.y, r3.y)), h.y);
                v[y - 2] = m;                     // in-place: feeds next pool
            }
            r0 = r1; r1 = r2; r2 = r3; r3 = h;
        }

        // ---- stage + bulk store section p+1 ----
        __syncthreads();                          // buffer b free for all

        float2* stg = b ? stg1 : stg0;
        #pragma unroll
        for (int y = 0; y < 32; ++y) stg[y * 16] = v[y];
        asm volatile("fence.proxy.async.shared::cta;" ::: "memory");
        __syncthreads();

        if (threadIdx.x == 0)
            bulk_store_ef(ob + (size_t)(p + 1) * NCHAN * HW, b ? s1 : s0);
    }

    // SMEM must outlive all pending bulk reads.
    if (threadIdx.x == 0)
        asm volatile("cp.async.bulk.wait_group.read 0;" ::: "memory");
    __syncthreads();
}

extern "C" void kernel_launch(void* const* d_in, const int* in_sizes, int n_in,
                              void* d_out, int out_size) {
    const float* x = (const float*)d_in[0];
    float* out     = (float*)d_out;
    cudaFuncSetAttribute(spp_kernel,
                         cudaFuncAttributeMaxDynamicSharedMemorySize, SMEM_BYTES);
    spp_kernel<<<PLANES / PLANES_PER_BLK, 32 * WARPS_PER_BLK, SMEM_BYTES>>>(x, out);
}

// round 11
// speedup vs baseline: 1.1367x; 1.1367x over previous
#include <cuda_runtime.h>
#include <math_constants.h>
#include <cstdint>

// SPP: out = concat(x, pool5(x), pool9(x), pool13(x)) along channels.
// Cascade: pool9 = pool5(pool5(x)), pool13 = pool5(pool9(x)), separable.
//
// Structure = R8 (best measured: 55.0us bench / 49.8us ncu / DRAM 70%):
// block = 8 contiguous planes, 4 warps; warp = 2 planes, width-16 shuffles,
// pair-max horizontal 5-max, register-ring vertical 5-max, in-place cascade;
// output drains via ONE 32 KB cp.async.bulk per section (L2 evict_first),
// double-buffered.
//
// R10 change: staging fused into compute. The vertical-max result is stored
// to the staging buffer at the moment it's produced (STS inside the compute
// loop) instead of a separate 32-iteration staging pass. Buffer-free sync
// moves BEFORE compute, so the bulk-recycle wait hides under the entire
// compute phase.
//
// x: (32, 512, 32, 32) f32 -> out: (32, 2048, 32, 32) f32.

#define NCHAN 512
#define HW 1024
#define PLANES (32 * 512)
#define WARPS_PER_BLK 4
#define PLANES_PER_BLK (WARPS_PER_BLK * 2)
#define SEC_FLOATS (PLANES_PER_BLK * HW)          // 8192 floats
#define SEC_BYTES  (SEC_FLOATS * 4)               // 32768 bytes
#define SMEM_BYTES (2 * SEC_BYTES)                // 64 KB

__device__ __forceinline__ uint32_t smem_u32(const void* p) {
    uint32_t a;
    asm("{ .reg .u64 t; cvta.to.shared.u64 t, %1; cvt.u32.u64 %0, t; }"
        : "=r"(a) : "l"(p));
    return a;
}

__device__ __forceinline__ void bulk_store_ef(const float* dst, uint32_t s) {
    asm volatile(
        "{\n\t"
        ".reg .b64 pol;\n\t"
        "createpolicy.fractional.L2::evict_first.b64 pol, 1.0;\n\t"
        "cp.async.bulk.global.shared::cta.bulk_group.L2::cache_hint "
        "[%0], [%1], %2, pol;\n\t"
        "}"
        :: "l"(dst), "r"(s), "n"(SEC_BYTES) : "memory");
    asm volatile("cp.async.bulk.commit_group;" ::: "memory");
}

__global__ __launch_bounds__(32 * WARPS_PER_BLK)
void spp_kernel(const float* __restrict__ x, float* __restrict__ out) {
    extern __shared__ float sbuf[];               // [2][SEC_FLOATS]

    const int lane = threadIdx.x & 31;
    const int wid  = threadIdx.x >> 5;
    const int sub  = lane >> 4;                   // plane within warp (0/1)
    const int l    = lane & 15;                   // column-pair index

    const int pl_local = wid * 2 + sub;           // 0..7 within block
    const int plane = blockIdx.x * PLANES_PER_BLK + pl_local;   // n*512+c
    const int n  = plane >> 9;
    const int c0 = (blockIdx.x * PLANES_PER_BLK) & (NCHAN - 1);

    const float2* __restrict__ xin =
        (const float2*)(x + (size_t)plane * HW) + l;
    const float* __restrict__ ob =
        out + ((size_t)n * (4 * NCHAN) + c0) * HW;

    // Lane's 2-column strip, all 32 rows, in registers.
    float2 v[32];
    #pragma unroll
    for (int y = 0; y < 32; ++y) v[y] = xin[y * 16];

    float2* stg0 = (float2*)(sbuf)              + pl_local * (HW / 2) + l;
    float2* stg1 = (float2*)(sbuf + SEC_FLOATS) + pl_local * (HW / 2) + l;
    const uint32_t s0 = smem_u32(sbuf);
    const uint32_t s1 = smem_u32(sbuf + SEC_FLOATS);

    // ---- section 0: pass-through via bulk store (buffer 0) ----
    #pragma unroll
    for (int y = 0; y < 32; ++y) stg0[y * 16] = v[y];
    asm volatile("fence.proxy.async.shared::cta;" ::: "memory");
    __syncthreads();
    if (threadIdx.x == 0) bulk_store_ef(ob, s0);

    const unsigned FULL = 0xffffffffu;
    const float NEG = -CUDART_INF_F;

    #pragma unroll
    for (int p = 0; p < 3; ++p) {
        // Section p+1 stages into buffer b = 1,0,1. Buffer b's previous
        // bulk consumer was issued two sections ago; retire it (allowing
        // the most recent group to stay in flight), then make buffer-free
        // visible to all warps BEFORE compute so the STS below are safe.
        const int b = (p + 1) & 1;
        if (p >= 1 && threadIdx.x == 0)
            asm volatile("cp.async.bulk.wait_group.read 1;" ::: "memory");
        __syncthreads();

        float2* stg = b ? stg1 : stg0;

        // ---- compute pool p; result stores fused into the loop ----
        float2 r0 = {NEG, NEG}, r1 = {NEG, NEG},
               r2 = {NEG, NEG}, r3 = {NEG, NEG};

        #pragma unroll
        for (int y = 0; y < 34; ++y) {
            float2 h;
            if (y < 32) {
                const float a = v[y].x, bb = v[y].y;
                const float pm = fmaxf(a, bb);
                const float lp = __shfl_up_sync  (FULL, pm, 1, 16);
                const float lb = __shfl_up_sync  (FULL, bb, 1, 16);
                const float ra = __shfl_down_sync(FULL, a,  1, 16);
                const float rp = __shfl_down_sync(FULL, pm, 1, 16);
                h.x = fmaxf(fmaxf(lp, pm), ra);   // cols 2l-2 .. 2l+2
                h.y = fmaxf(fmaxf(lb, pm), rp);   // cols 2l-1 .. 2l+3
            } else {
                h.x = NEG; h.y = NEG;             // bottom padding rows
            }
            if (y >= 2) {
                float2 m;
                m.x = fmaxf(fmaxf(fmaxf(r0.x, r1.x), fmaxf(r2.x, r3.x)), h.x);
                m.y = fmaxf(fmaxf(fmaxf(r0.y, r1.y), fmaxf(r2.y, r3.y)), h.y);
                v[y - 2] = m;                     // in-place: feeds next pool
                stg[(y - 2) * 16] = m;            // fused staging STS
            }
            r0 = r1; r1 = r2; r2 = r3; r3 = h;
        }

        // ---- publish + bulk store section p+1 ----
        asm volatile("fence.proxy.async.shared::cta;" ::: "memory");
        __syncthreads();
        if (threadIdx.x == 0)
            bulk_store_ef(ob + (size_t)(p + 1) * NCHAN * HW, b ? s1 : s0);
    }

    // SMEM must outlive all pending bulk reads.
    if (threadIdx.x == 0)
        asm volatile("cp.async.bulk.wait_group.read 0;" ::: "memory");
    __syncthreads();
}

extern "C" void kernel_launch(void* const* d_in, const int* in_sizes, int n_in,
                              void* d_out, int out_size) {
    const float* x = (const float*)d_in[0];
    float* out     = (float*)d_out;
    cudaFuncSetAttribute(spp_kernel,
                         cudaFuncAttributeMaxDynamicSharedMemorySize, SMEM_BYTES);
    spp_kernel<<<PLANES / PLANES_PER_BLK, 32 * WARPS_PER_BLK, SMEM_BYTES>>>(x, out);
}